// round 15
// baseline (speedup 1.0000x reference)
#include <cuda_runtime.h>
#include <cuda_fp16.h>
#include <cstdint>

#define DD   512
#define NB   4
#define LQ   128
#define LM   256
#define NDP  256   // d-pairs

// Scratch (allocation-free rule: __device__ globals)
__device__ float    g_q[NB * LQ * DD];          // q = input_emb @ Wq^T + b0 (fp32)
__device__ uint32_t g_mp4[NB * 64 * LM * 4];    // mp half2, [n][dp4][m][slot0..3]
__device__ float    g_sc[NB * LQ * LM];         // raw scores (pre-mask/softmax)

__device__ __forceinline__ void mma_tf32(
    float& c0, float& c1, float& c2, float& c3,
    uint32_t a0, uint32_t a1, uint32_t a2, uint32_t a3,
    uint32_t b0, uint32_t b1)
{
    asm volatile(
        "mma.sync.aligned.m16n8k8.row.col.f32.tf32.tf32.f32 "
        "{%0,%1,%2,%3}, {%4,%5,%6,%7}, {%8,%9}, {%0,%1,%2,%3};"
        : "+f"(c0), "+f"(c1), "+f"(c2), "+f"(c3)
        : "r"(a0), "r"(a1), "r"(a2), "r"(a3), "r"(b0), "r"(b1));
}

__device__ __forceinline__ void cpa16(uint32_t dst, const void* src)
{
    asm volatile("cp.async.cg.shared.global [%0], [%1], 16;\n"
                 :: "r"(dst), "l"(src));
}

__device__ __forceinline__ __half2 tanh2(__half2 x)
{
    uint32_t xi = *(uint32_t*)&x, ri;
    asm("tanh.approx.f16x2 %0, %1;" : "=r"(ri) : "r"(xi));
    return *(__half2*)&ri;
}

__device__ __forceinline__ __half2 H2(uint32_t u) { return *(__half2*)&u; }

// ---------------------------------------------------------------------------
// Per-batch tensor-core GEMM (tf32, cp.async, XOR swizzle). 96 blocks.
// PDL: triggers early; no dependency sync (reads only harness inputs).
// ---------------------------------------------------------------------------
__global__ __launch_bounds__(128, 6) void gemm_tc_kernel(
    int n,
    const float* __restrict__ inp, const float* __restrict__ mem,
    const float* __restrict__ W0, const float* __restrict__ b0)
{
    cudaTriggerProgrammaticLaunchCompletion();

    __shared__ float As[2][32 * 32];
    __shared__ float Bs[2][64 * 32];

    const int sub = blockIdx.x;
    const float* A;
    int off, r0, e0;
    bool isq;
    if (sub < 32) {
        A = inp; off = 0; isq = true;
        r0 = (n * 4 + (sub >> 3)) * 32; e0 = (sub & 7) * 64;
    } else {
        const int s2 = sub - 32;
        A = mem; off = DD; isq = false;
        r0 = (n * 8 + (s2 >> 3)) * 32; e0 = (s2 & 7) * 64;
    }

    const int t = threadIdx.x;
    const int wid = t >> 5, lane = t & 31;
    const int lx = lane & 3, ly = lane >> 2;
    const int swz = 4 * ly;

    const uint32_t sAs = (uint32_t)__cvta_generic_to_shared(As);
    const uint32_t sBs = (uint32_t)__cvta_generic_to_shared(Bs);

    float c[2][2][4];
#pragma unroll
    for (int mt = 0; mt < 2; mt++)
#pragma unroll
        for (int nt = 0; nt < 2; nt++)
#pragma unroll
            for (int i = 0; i < 4; i++) c[mt][nt][i] = 0.f;

    const float* aptr = A + (size_t)r0 * DD;
    const float* bptr = W0 + (size_t)e0 * (2 * DD) + off;

    auto load_stage = [&](int s, int k0) {
#pragma unroll
        for (int i = 0; i < 2; i++) {
            const int cid = 2 * t + i;
            const int row = cid >> 3, cc = (cid & 7) * 4;
            const int pc = cc ^ ((row & 7) * 4);
            cpa16(sAs + (uint32_t)((s * 1024 + row * 32 + pc) * 4),
                  aptr + (size_t)row * DD + k0 + cc);
        }
#pragma unroll
        for (int i = 0; i < 4; i++) {
            const int cid = t + i * 128;
            const int row = cid >> 3, cc = (cid & 7) * 4;
            const int pc = cc ^ ((row & 7) * 4);
            cpa16(sBs + (uint32_t)((s * 2048 + row * 32 + pc) * 4),
                  bptr + (size_t)row * (2 * DD) + k0 + cc);
        }
        asm volatile("cp.async.commit_group;\n" ::: "memory");
    };

    load_stage(0, 0);

    const uint32_t* AsU = (const uint32_t*)As;
    const uint32_t* BsU = (const uint32_t*)Bs;

    for (int it = 0; it < 16; it++) {
        if (it + 1 < 16) load_stage((it + 1) & 1, (it + 1) * 32);
        else asm volatile("cp.async.commit_group;\n" ::: "memory");
        asm volatile("cp.async.wait_group 1;\n" ::: "memory");
        __syncthreads();

        const int s = it & 1;
        const uint32_t* Ab = AsU + s * 1024;
        const uint32_t* Bb = BsU + s * 2048;
#pragma unroll
        for (int k8 = 0; k8 < 4; k8++) {
            const int c0 = (k8 * 8 + lx) ^ swz;
            const int c1 = c0 ^ 4;
            uint32_t a[2][4], b[2][2];
#pragma unroll
            for (int mt = 0; mt < 2; mt++) {
                const int rA = mt * 16 + ly;
                a[mt][0] = Ab[rA * 32 + c0];
                a[mt][1] = Ab[(rA + 8) * 32 + c0];
                a[mt][2] = Ab[rA * 32 + c1];
                a[mt][3] = Ab[(rA + 8) * 32 + c1];
            }
#pragma unroll
            for (int nt = 0; nt < 2; nt++) {
                const int rB = wid * 16 + nt * 8 + ly;
                b[nt][0] = Bb[rB * 32 + c0];
                b[nt][1] = Bb[rB * 32 + c1];
            }
#pragma unroll
            for (int mt = 0; mt < 2; mt++)
#pragma unroll
                for (int nt = 0; nt < 2; nt++)
                    mma_tf32(c[mt][nt][0], c[mt][nt][1], c[mt][nt][2], c[mt][nt][3],
                             a[mt][0], a[mt][1], a[mt][2], a[mt][3],
                             b[nt][0], b[nt][1]);
        }
        __syncthreads();
    }

    // epilogue
#pragma unroll
    for (int mt = 0; mt < 2; mt++) {
#pragma unroll
        for (int nt = 0; nt < 2; nt++) {
            const int col = e0 + wid * 16 + nt * 8 + 2 * lx;
            const int rA = r0 + mt * 16 + ly;
            if (isq) {
                float bx0 = b0[col], bx1 = b0[col + 1];
                float2 v0 = make_float2(c[mt][nt][0] + bx0, c[mt][nt][1] + bx1);
                float2 v1 = make_float2(c[mt][nt][2] + bx0, c[mt][nt][3] + bx1);
                *(float2*)&g_q[(size_t)rA * DD + col]       = v0;
                *(float2*)&g_q[(size_t)(rA + 8) * DD + col] = v1;
            } else {
                const int n_ = rA >> 8;
                const int m_ = rA & 255;
                const int dp = col >> 1;
                const int dp4 = dp >> 2, slot = dp & 3;
                __half2 u0 = __floats2half2_rn(c[mt][nt][0], c[mt][nt][1]);
                __half2 u1 = __floats2half2_rn(c[mt][nt][2], c[mt][nt][3]);
                uint32_t* base = g_mp4 + (size_t)n_ * (64 * LM * 4) + dp4 * (LM * 4);
                base[m_ * 4 + slot]       = *(uint32_t*)&u0;
                base[(m_ + 8) * 4 + slot] = *(uint32_t*)&u1;
            }
        }
    }
}

// ---------------------------------------------------------------------------
// Per-batch score kernel. 128 blocks: l-tile(32, 4 l) x m-quarter(4, 64 m).
// PDL: triggers early, then waits for predecessor (gemm of same batch).
// ---------------------------------------------------------------------------
__global__ __launch_bounds__(256, 4) void score_kernel(
    int n, const float* __restrict__ w1v, const float* __restrict__ b1)
{
    cudaTriggerProgrammaticLaunchCompletion();
    cudaGridDependencySynchronize();   // g_q / g_mp4 of batch n ready

    __shared__ uint4 sq[4][64];   // [l][dp4]: 4 q-half2
    __shared__ uint4 sw[64];      // [dp4]: 4 w1-half2

    const int b = blockIdx.x;
    const int l0 = (b >> 2) * 4;
    const int mq = b & 3;
    const int t = threadIdx.x;
    const int wid = t >> 5, lane = t & 31;

    {
        const int l = t >> 6, dp4 = t & 63;
        const float* qp = &g_q[(size_t)(n * LQ + l0 + l) * DD + dp4 * 8];
        float4 v0 = *(const float4*)qp;
        float4 v1 = *(const float4*)(qp + 4);
        __half2 h0 = __floats2half2_rn(v0.x, v0.y);
        __half2 h1 = __floats2half2_rn(v0.z, v0.w);
        __half2 h2 = __floats2half2_rn(v1.x, v1.y);
        __half2 h3 = __floats2half2_rn(v1.z, v1.w);
        sq[l][dp4] = make_uint4(*(uint32_t*)&h0, *(uint32_t*)&h1,
                                *(uint32_t*)&h2, *(uint32_t*)&h3);
        if (t < 64) {
            const float* wp = &w1v[t * 8];
            float4 w0 = *(const float4*)wp;
            float4 w1f = *(const float4*)(wp + 4);
            __half2 g0 = __floats2half2_rn(w0.x, w0.y);
            __half2 g1 = __floats2half2_rn(w0.z, w0.w);
            __half2 g2 = __floats2half2_rn(w1f.x, w1f.y);
            __half2 g3 = __floats2half2_rn(w1f.z, w1f.w);
            sw[t] = make_uint4(*(uint32_t*)&g0, *(uint32_t*)&g1,
                               *(uint32_t*)&g2, *(uint32_t*)&g3);
        }
    }
    __syncthreads();

    const int l = wid & 3;
    const int m = mq * 64 + (wid >> 2) * 32 + lane;
    const uint4* mp4 = (const uint4*)g_mp4 + (size_t)n * (64 * LM);

    float s = 0.f;
#pragma unroll 4
    for (int g = 0; g < 16; g++) {
        uint4 Av[4];
#pragma unroll
        for (int j = 0; j < 4; j++)
            Av[j] = mp4[(g * 4 + j) * LM + m];
        __half2 a0 = __float2half2_rn(0.f), a1 = __float2half2_rn(0.f);
#pragma unroll
        for (int j = 0; j < 4; j++) {
            const int dp4 = g * 4 + j;
            const uint4 qv = sq[l][dp4];
            const uint4 wv = sw[dp4];
            a0 = __hfma2(H2(wv.x), tanh2(__hadd2(H2(qv.x), H2(Av[j].x))), a0);
            a1 = __hfma2(H2(wv.y), tanh2(__hadd2(H2(qv.y), H2(Av[j].y))), a1);
            a0 = __hfma2(H2(wv.z), tanh2(__hadd2(H2(qv.z), H2(Av[j].z))), a0);
            a1 = __hfma2(H2(wv.w), tanh2(__hadd2(H2(qv.w), H2(Av[j].w))), a1);
        }
        float2 f = __half22float2(__hadd2(a0, a1));
        s += f.x + f.y;
    }

    g_sc[(size_t)(n * LQ + l0 + l) * LM + m] = s + b1[0];
}

// ---------------------------------------------------------------------------
// Per-batch softmax + output. 128 blocks: l-tile(16, 8 rows) x d-split(8, 64).
// PDL: triggers early, then waits for predecessor (score of same batch).
// ---------------------------------------------------------------------------
__global__ __launch_bounds__(256) void out_kernel(
    int n, const float* __restrict__ mem, const unsigned int* __restrict__ mask,
    float* __restrict__ out)
{
    cudaTriggerProgrammaticLaunchCompletion();
    cudaGridDependencySynchronize();   // g_sc of batch n ready

    __shared__ float att[8][LM];

    const int b = blockIdx.x;
    const int l0 = (b >> 3) * 8;
    const int d0 = (b & 7) * 64;
    const int t = threadIdx.x;
    const int w = t >> 5, lane = t & 31;

    {
        const int l = w;
        const float* srow = g_sc + (size_t)(n * LQ + l0 + l) * LM;
        const unsigned int* mrow = mask + (size_t)(n * LQ + l0 + l) * LM;
        const float NEG = -3.402823466e38f;
        float s[8];
        float mx = NEG;
#pragma unroll
        for (int k = 0; k < 8; k++) {
            int m = lane + 32 * k;
            float v = srow[m];
            if (mrow[m] == 0u) v = NEG;   // bool promoted: nonzero bits == true
            s[k] = v;
            mx = fmaxf(mx, v);
        }
#pragma unroll
        for (int o = 16; o > 0; o >>= 1)
            mx = fmaxf(mx, __shfl_xor_sync(0xffffffffu, mx, o));
        float sum = 0.f;
#pragma unroll
        for (int k = 0; k < 8; k++) {
            s[k] = __expf(s[k] - mx);
            sum += s[k];
        }
#pragma unroll
        for (int o = 16; o > 0; o >>= 1)
            sum += __shfl_xor_sync(0xffffffffu, sum, o);
        const float inv = 1.f / sum;
#pragma unroll
        for (int k = 0; k < 8; k++)
            att[l][lane + 32 * k] = s[k] * inv;
    }
    __syncthreads();

    {
        const int r = w;
        const int dbase = d0 + 2 * lane;
        const float* memn = mem + (size_t)n * LM * DD + dbase;
        float ox = 0.f, oy = 0.f;
        for (int mb = 0; mb < LM; mb += 8) {
            float2 v[8];
#pragma unroll
            for (int j = 0; j < 8; j++)
                v[j] = *(const float2*)&memn[(size_t)(mb + j) * DD];
#pragma unroll
            for (int j = 0; j < 8; j++) {
                const float a = att[r][mb + j];
                ox = fmaf(a, v[j].x, ox);
                oy = fmaf(a, v[j].y, oy);
            }
        }
        *(float2*)&out[(size_t)(n * LQ + l0 + r) * DD + dbase] = make_float2(ox, oy);
    }
}

// ---------------------------------------------------------------------------
// Launch: single stream, PDL on every kernel. Order interleaves batches so
// score(n) [MUFU] overlaps gemm(n+1) [tensor] and out(n-1) [L2/FMA]:
//   g0 s0 g1 s1 o0 g2 s2 o1 g3 s3 o2 o3
// Completion remains stream-ordered under PDL, so each consumer's
// GridDependencySynchronize (wait on immediate predecessor) transitively
// covers its true producer. No streams/events/allocations.
// ---------------------------------------------------------------------------
template <typename... Args>
static inline void launch_pdl(void (*kern)(Args...), int grid, int block, Args... args)
{
    cudaLaunchAttribute attr[1];
    attr[0].id = cudaLaunchAttributeProgrammaticStreamSerialization;
    attr[0].val.programmaticStreamSerializationAllowed = 1;
    cudaLaunchConfig_t cfg{};
    cfg.gridDim = dim3(grid, 1, 1);
    cfg.blockDim = dim3(block, 1, 1);
    cfg.dynamicSmemBytes = 0;
    cfg.stream = 0;
    cfg.attrs = attr;
    cfg.numAttrs = 1;
    cudaLaunchKernelEx(&cfg, kern, args...);
}

extern "C" void kernel_launch(void* const* d_in, const int* in_sizes, int n_in,
                              void* d_out, int out_size)
{
    const float*        inp  = (const float*)d_in[0];        // (4,128,512)
    const float*        mem  = (const float*)d_in[1];        // (4,256,512)
    const unsigned int* mask = (const unsigned int*)d_in[2]; // (4,128,256) bool->4B
    const float*        W0   = (const float*)d_in[3];        // (512,1024)
    const float*        b0   = (const float*)d_in[4];        // (512)
    const float*        w1   = (const float*)d_in[5];        // (1,512)
    const float*        b1   = (const float*)d_in[6];        // (1)
    float* out = (float*)d_out;                              // (4,128,512)

    launch_pdl(gemm_tc_kernel, 96, 128, 0, inp, mem, W0, b0);
    launch_pdl(score_kernel,  128, 256, 0, w1, b1);
    launch_pdl(gemm_tc_kernel, 96, 128, 1, inp, mem, W0, b0);
    launch_pdl(score_kernel,  128, 256, 1, w1, b1);
    launch_pdl(out_kernel,    128, 256, 0, mem, mask, out);
    launch_pdl(gemm_tc_kernel, 96, 128, 2, inp, mem, W0, b0);
    launch_pdl(score_kernel,  128, 256, 2, w1, b1);
    launch_pdl(out_kernel,    128, 256, 1, mem, mask, out);
    launch_pdl(gemm_tc_kernel, 96, 128, 3, inp, mem, W0, b0);
    launch_pdl(score_kernel,  128, 256, 3, w1, b1);
    launch_pdl(out_kernel,    128, 256, 2, mem, mask, out);
    launch_pdl(out_kernel,    128, 256, 3, mem, mask, out);
}

// round 17
// speedup vs baseline: 2.1561x; 2.1561x over previous
#include <cuda_runtime.h>
#include <cuda_fp16.h>
#include <cstdint>

#define DD   512
#define NB   4
#define LQ   128
#define LM   256
#define NDP  256   // d-pairs

// Scratch (allocation-free rule: __device__ globals)
__device__ float    g_q[NB * LQ * DD];          // q = input_emb @ Wq^T + b0 (fp32)
__device__ uint32_t g_mp4[NB * 64 * LM * 4];    // mp half2, [n][dp4][m][slot0..3]
__device__ float    g_sc[NB * LQ * LM];         // raw scores (pre-mask/softmax)

__device__ __forceinline__ void mma_tf32(
    float& c0, float& c1, float& c2, float& c3,
    uint32_t a0, uint32_t a1, uint32_t a2, uint32_t a3,
    uint32_t b0, uint32_t b1)
{
    asm volatile(
        "mma.sync.aligned.m16n8k8.row.col.f32.tf32.tf32.f32 "
        "{%0,%1,%2,%3}, {%4,%5,%6,%7}, {%8,%9}, {%0,%1,%2,%3};"
        : "+f"(c0), "+f"(c1), "+f"(c2), "+f"(c3)
        : "r"(a0), "r"(a1), "r"(a2), "r"(a3), "r"(b0), "r"(b1));
}

__device__ __forceinline__ void cpa16(uint32_t dst, const void* src)
{
    asm volatile("cp.async.cg.shared.global [%0], [%1], 16;\n"
                 :: "r"(dst), "l"(src));
}

__device__ __forceinline__ __half2 tanh2(__half2 x)
{
    uint32_t xi = *(uint32_t*)&x, ri;
    asm("tanh.approx.f16x2 %0, %1;" : "=r"(ri) : "r"(xi));
    return *(__half2*)&ri;
}

__device__ __forceinline__ __half2 H2(uint32_t u) { return *(__half2*)&u; }

// ---------------------------------------------------------------------------
// Tensor-core GEMM (tf32, cp.async double-buffered, XOR-swizzled smem).
// q-part  (blocks 0..127)  : g_q fp32, + bias
// mp-part (blocks 128..383): g_mp4 packed half2 [n][dp4][m][slot]
// (R12 kernel, verbatim.)
// ---------------------------------------------------------------------------
__global__ __launch_bounds__(128, 6) void gemm_tc_kernel(
    const float* __restrict__ inp, const float* __restrict__ mem,
    const float* __restrict__ W0, const float* __restrict__ b0)
{
    __shared__ float As[2][32 * 32];
    __shared__ float Bs[2][64 * 32];

    const int bx = blockIdx.x;
    const float* A;
    int off, r0, e0;
    bool isq;
    if (bx < 128) {
        A = inp; off = 0; isq = true;
        r0 = (bx >> 3) * 32; e0 = (bx & 7) * 64;
    } else {
        const int i = bx - 128;
        A = mem; off = DD; isq = false;
        r0 = (i >> 3) * 32; e0 = (i & 7) * 64;
    }

    const int t = threadIdx.x;
    const int wid = t >> 5, lane = t & 31;
    const int lx = lane & 3, ly = lane >> 2;
    const int swz = 4 * ly;

    const uint32_t sAs = (uint32_t)__cvta_generic_to_shared(As);
    const uint32_t sBs = (uint32_t)__cvta_generic_to_shared(Bs);

    float c[2][2][4];
#pragma unroll
    for (int mt = 0; mt < 2; mt++)
#pragma unroll
        for (int nt = 0; nt < 2; nt++)
#pragma unroll
            for (int i = 0; i < 4; i++) c[mt][nt][i] = 0.f;

    const float* aptr = A + (size_t)r0 * DD;
    const float* bptr = W0 + (size_t)e0 * (2 * DD) + off;

    auto load_stage = [&](int s, int k0) {
#pragma unroll
        for (int i = 0; i < 2; i++) {
            const int cid = 2 * t + i;
            const int row = cid >> 3, cc = (cid & 7) * 4;
            const int pc = cc ^ ((row & 7) * 4);
            cpa16(sAs + (uint32_t)((s * 1024 + row * 32 + pc) * 4),
                  aptr + (size_t)row * DD + k0 + cc);
        }
#pragma unroll
        for (int i = 0; i < 4; i++) {
            const int cid = t + i * 128;
            const int row = cid >> 3, cc = (cid & 7) * 4;
            const int pc = cc ^ ((row & 7) * 4);
            cpa16(sBs + (uint32_t)((s * 2048 + row * 32 + pc) * 4),
                  bptr + (size_t)row * (2 * DD) + k0 + cc);
        }
        asm volatile("cp.async.commit_group;\n" ::: "memory");
    };

    load_stage(0, 0);

    const uint32_t* AsU = (const uint32_t*)As;
    const uint32_t* BsU = (const uint32_t*)Bs;

    for (int it = 0; it < 16; it++) {
        if (it + 1 < 16) load_stage((it + 1) & 1, (it + 1) * 32);
        else asm volatile("cp.async.commit_group;\n" ::: "memory");
        asm volatile("cp.async.wait_group 1;\n" ::: "memory");
        __syncthreads();

        const int s = it & 1;
        const uint32_t* Ab = AsU + s * 1024;
        const uint32_t* Bb = BsU + s * 2048;
#pragma unroll
        for (int k8 = 0; k8 < 4; k8++) {
            const int c0 = (k8 * 8 + lx) ^ swz;
            const int c1 = c0 ^ 4;
            uint32_t a[2][4], b[2][2];
#pragma unroll
            for (int mt = 0; mt < 2; mt++) {
                const int rA = mt * 16 + ly;
                a[mt][0] = Ab[rA * 32 + c0];
                a[mt][1] = Ab[(rA + 8) * 32 + c0];
                a[mt][2] = Ab[rA * 32 + c1];
                a[mt][3] = Ab[(rA + 8) * 32 + c1];
            }
#pragma unroll
            for (int nt = 0; nt < 2; nt++) {
                const int rB = wid * 16 + nt * 8 + ly;
                b[nt][0] = Bb[rB * 32 + c0];
                b[nt][1] = Bb[rB * 32 + c1];
            }
#pragma unroll
            for (int mt = 0; mt < 2; mt++)
#pragma unroll
                for (int nt = 0; nt < 2; nt++)
                    mma_tf32(c[mt][nt][0], c[mt][nt][1], c[mt][nt][2], c[mt][nt][3],
                             a[mt][0], a[mt][1], a[mt][2], a[mt][3],
                             b[nt][0], b[nt][1]);
        }
        __syncthreads();
    }

    // epilogue
#pragma unroll
    for (int mt = 0; mt < 2; mt++) {
#pragma unroll
        for (int nt = 0; nt < 2; nt++) {
            const int col = e0 + wid * 16 + nt * 8 + 2 * lx;
            const int rA = r0 + mt * 16 + ly;
            if (isq) {
                float bx0 = b0[col], bx1 = b0[col + 1];
                float2 v0 = make_float2(c[mt][nt][0] + bx0, c[mt][nt][1] + bx1);
                float2 v1 = make_float2(c[mt][nt][2] + bx0, c[mt][nt][3] + bx1);
                *(float2*)&g_q[(size_t)rA * DD + col]       = v0;
                *(float2*)&g_q[(size_t)(rA + 8) * DD + col] = v1;
            } else {
                const int n_ = rA >> 8;
                const int m_ = rA & 255;
                const int dp = col >> 1;
                const int dp4 = dp >> 2, slot = dp & 3;
                __half2 u0 = __floats2half2_rn(c[mt][nt][0], c[mt][nt][1]);
                __half2 u1 = __floats2half2_rn(c[mt][nt][2], c[mt][nt][3]);
                uint32_t* base = g_mp4 + (size_t)n_ * (64 * LM * 4) + dp4 * (LM * 4);
                base[m_ * 4 + slot]       = *(uint32_t*)&u0;
                base[(m_ + 8) * 4 + slot] = *(uint32_t*)&u1;
            }
        }
    }
}

// ---------------------------------------------------------------------------
// Score kernel (register double-buffered, prefetch distance 2):
//   g_sc[n,l,m] = b1 + sum_d w1[d]*tanh(q[n,l,d]+mp[n,m,d])
// grid = 1024 blocks: n(4) x l-tile(32, 4 l) x m-octant(8, 32 m).
// 128 threads = 4 warps: warp w -> l = l0+w; lane -> m = m0+lane.
// All 4 warps read the SAME mp addresses (L1 reuse); loads for group g+2
// are issued before computing group g (stalls hidden behind ~28 instrs).
// Arithmetic identical to R12 (same chains/order) -> rel_err must match.
// ---------------------------------------------------------------------------
__global__ __launch_bounds__(128, 8) void score_kernel(
    const float* __restrict__ w1v, const float* __restrict__ b1)
{
    __shared__ uint4 sq[4][64];   // [l][dp4]: 4 q-half2
    __shared__ uint4 sw[64];      // [dp4]: 4 w1-half2

    const int b = blockIdx.x;
    const int n = b >> 8;
    const int rem = b & 255;
    const int l0 = (rem >> 3) * 4;
    const int m0 = (rem & 7) * 32;
    const int t = threadIdx.x;
    const int wid = t >> 5, lane = t & 31;

    // fill q table (256 entries, 2 per thread) + w1 table (64)
#pragma unroll
    for (int i = 0; i < 2; i++) {
        const int idx = t + i * 128;
        const int l = idx >> 6, dp4 = idx & 63;
        const float* qp = &g_q[(size_t)(n * LQ + l0 + l) * DD + dp4 * 8];
        float4 v0 = *(const float4*)qp;
        float4 v1 = *(const float4*)(qp + 4);
        __half2 h0 = __floats2half2_rn(v0.x, v0.y);
        __half2 h1 = __floats2half2_rn(v0.z, v0.w);
        __half2 h2 = __floats2half2_rn(v1.x, v1.y);
        __half2 h3 = __floats2half2_rn(v1.z, v1.w);
        sq[l][dp4] = make_uint4(*(uint32_t*)&h0, *(uint32_t*)&h1,
                                *(uint32_t*)&h2, *(uint32_t*)&h3);
    }
    if (t < 64) {
        const float* wp = &w1v[t * 8];
        float4 w0 = *(const float4*)wp;
        float4 w1f = *(const float4*)(wp + 4);
        __half2 g0 = __floats2half2_rn(w0.x, w0.y);
        __half2 g1 = __floats2half2_rn(w0.z, w0.w);
        __half2 g2 = __floats2half2_rn(w1f.x, w1f.y);
        __half2 g3 = __floats2half2_rn(w1f.z, w1f.w);
        sw[t] = make_uint4(*(uint32_t*)&g0, *(uint32_t*)&g1,
                           *(uint32_t*)&g2, *(uint32_t*)&g3);
    }
    __syncthreads();

    const int l = wid;
    const int m = m0 + lane;
    const uint4* mp4 = (const uint4*)g_mp4 + (size_t)n * (64 * LM) + m;

    uint4 bufA[4], bufB[4];
#pragma unroll
    for (int j = 0; j < 4; j++) bufA[j] = mp4[(size_t)(0 * 4 + j) * LM];
#pragma unroll
    for (int j = 0; j < 4; j++) bufB[j] = mp4[(size_t)(1 * 4 + j) * LM];

    float s = 0.f;
#pragma unroll
    for (int g = 0; g < 16; g++) {
        const uint4* D = (g & 1) ? bufB : bufA;
        uint4* P = (g & 1) ? bufB : bufA;   // buffer being freed this iter
        // compute group g, accumulate (identical chain structure to R12)
        __half2 a0 = __float2half2_rn(0.f), a1 = __float2half2_rn(0.f);
#pragma unroll
        for (int j = 0; j < 4; j++) {
            const int dp4 = g * 4 + j;
            const uint4 qv = sq[l][dp4];
            const uint4 wv = sw[dp4];
            const uint4 Av = D[j];
            a0 = __hfma2(H2(wv.x), tanh2(__hadd2(H2(qv.x), H2(Av.x))), a0);
            a1 = __hfma2(H2(wv.y), tanh2(__hadd2(H2(qv.y), H2(Av.y))), a1);
            a0 = __hfma2(H2(wv.z), tanh2(__hadd2(H2(qv.z), H2(Av.z))), a0);
            a1 = __hfma2(H2(wv.w), tanh2(__hadd2(H2(qv.w), H2(Av.w))), a1);
        }
        float2 f = __half22float2(__hadd2(a0, a1));
        s += f.x + f.y;
        // prefetch group g+2 into the buffer just consumed
        if (g + 2 < 16) {
#pragma unroll
            for (int j = 0; j < 4; j++)
                P[j] = mp4[(size_t)((g + 2) * 4 + j) * LM];
        }
    }

    g_sc[(size_t)(n * LQ + l0 + l) * LM + m] = s + b1[0];
}

// ---------------------------------------------------------------------------
// Softmax + output (R12 kernel, verbatim). grid = 512 blocks:
// n(4) x l-tile(16, 8 rows) x d-split(8, 64 d's), 256 threads.
// ---------------------------------------------------------------------------
__global__ __launch_bounds__(256) void out_kernel(
    const float* __restrict__ mem, const unsigned int* __restrict__ mask,
    float* __restrict__ out)
{
    __shared__ float att[8][LM];

    const int b = blockIdx.x;
    const int n = b >> 7;
    const int rem = b & 127;
    const int l0 = (rem >> 3) * 8;
    const int d0 = (rem & 7) * 64;
    const int t = threadIdx.x;
    const int w = t >> 5, lane = t & 31;

    {
        const int l = w;
        const float* srow = g_sc + (size_t)(n * LQ + l0 + l) * LM;
        const unsigned int* mrow = mask + (size_t)(n * LQ + l0 + l) * LM;
        const float NEG = -3.402823466e38f;
        float s[8];
        float mx = NEG;
#pragma unroll
        for (int k = 0; k < 8; k++) {
            int m = lane + 32 * k;
            float v = srow[m];
            if (mrow[m] == 0u) v = NEG;   // bool promoted: nonzero bits == true
            s[k] = v;
            mx = fmaxf(mx, v);
        }
#pragma unroll
        for (int o = 16; o > 0; o >>= 1)
            mx = fmaxf(mx, __shfl_xor_sync(0xffffffffu, mx, o));
        float sum = 0.f;
#pragma unroll
        for (int k = 0; k < 8; k++) {
            s[k] = __expf(s[k] - mx);
            sum += s[k];
        }
#pragma unroll
        for (int o = 16; o > 0; o >>= 1)
            sum += __shfl_xor_sync(0xffffffffu, sum, o);
        const float inv = 1.f / sum;
#pragma unroll
        for (int k = 0; k < 8; k++)
            att[l][lane + 32 * k] = s[k] * inv;
    }
    __syncthreads();

    {
        const int r = w;
        const int dbase = d0 + 2 * lane;
        const float* memn = mem + (size_t)n * LM * DD + dbase;
        float ox = 0.f, oy = 0.f;
        for (int mb = 0; mb < LM; mb += 8) {
            float2 v[8];
#pragma unroll
            for (int j = 0; j < 8; j++)
                v[j] = *(const float2*)&memn[(size_t)(mb + j) * DD];
#pragma unroll
            for (int j = 0; j < 8; j++) {
                const float a = att[r][mb + j];
                ox = fmaf(a, v[j].x, ox);
                oy = fmaf(a, v[j].y, oy);
            }
        }
        *(float2*)&out[(size_t)(n * LQ + l0 + r) * DD + dbase] = make_float2(ox, oy);
    }
}

extern "C" void kernel_launch(void* const* d_in, const int* in_sizes, int n_in,
                              void* d_out, int out_size)
{
    const float*        inp  = (const float*)d_in[0];        // (4,128,512)
    const float*        mem  = (const float*)d_in[1];        // (4,256,512)
    const unsigned int* mask = (const unsigned int*)d_in[2]; // (4,128,256) bool->4B
    const float*        W0   = (const float*)d_in[3];        // (512,1024)
    const float*        b0   = (const float*)d_in[4];        // (512)
    const float*        w1   = (const float*)d_in[5];        // (1,512)
    const float*        b1   = (const float*)d_in[6];        // (1)
    float* out = (float*)d_out;                              // (4,128,512)

    gemm_tc_kernel<<<384, 128>>>(inp, mem, W0, b0);
    score_kernel<<<1024, 128>>>(w1, b1);
    out_kernel<<<512, 256>>>(mem, mask, out);
}